// round 4
// baseline (speedup 1.0000x reference)
#include <cuda_runtime.h>

#define NN   100000
#define FC   128
#define NE   1600000
#define NG   512
#define NOUT 10

// Scratch (device globals; float4 => guaranteed 16B alignment for red.v4)
__device__ float4 g_agg [(size_t)NN * (FC / 4)];
__device__ float4 g_ha  [(size_t)NN * (FC / 4)];
__device__ float4 g_hb  [(size_t)NN * (FC / 4)];
__device__ float4 g_pool[NG * (FC / 4)];
__device__ float  g_cnt [NG];
__device__ int    g_is64;

// ---------------------------------------------------------------------------
// Index dtype detection: if the first 512 int64-interpreted values of
// edge_index are all in [0, NN), the buffer is int64; otherwise int32
// (an int32 pair with nonzero hi word reads as >= 2^32).
// ---------------------------------------------------------------------------
__global__ void detect_kernel(const long long* __restrict__ ei)
{
    __shared__ int ok;
    if (threadIdx.x == 0) ok = 1;
    __syncthreads();
    long long v = ei[threadIdx.x];           // 512 threads
    if (v < 0 || v >= NN) atomicAnd(&ok, 0);
    __syncthreads();
    if (threadIdx.x == 0) g_is64 = ok;
}

__device__ __forceinline__ long long load_idx(const void* base, int i, int is64)
{
    if (is64) return ((const long long*)base)[i];
    return (long long)((const int*)base)[i];
}

// ---------------------------------------------------------------------------
// Edge scatter-add: agg[dst] += x[src]. One warp per edge, one float4 per lane.
// Block = 256 threads = 8 edges.
// ---------------------------------------------------------------------------
__global__ void scatter_kernel(const float4* __restrict__ x,
                               const void* __restrict__ ei,
                               float4* __restrict__ agg)
{
    int e = blockIdx.x * 8 + (threadIdx.x >> 5);
    if (e >= NE) return;
    int c = threadIdx.x & 31;
    int is64 = g_is64;
    long long s = load_idx(ei, e, is64);
    long long d = load_idx(ei, e + NE, is64);   // dst = second row of [2, NE]
    float4 v = x[s * 32 + c];
    float4* p = agg + d * 32 + c;
    asm volatile("red.global.add.v4.f32 [%0], {%1,%2,%3,%4};"
                 :: "l"(p), "f"(v.x), "f"(v.y), "f"(v.z), "f"(v.w)
                 : "memory");
}

// ---------------------------------------------------------------------------
// Fused GraphConv GEMM: out = (relu?)(A @ Wrel + X @ Wroot + b)
// Block: 256 threads, 64 rows x 128 cols tile. Both weights resident in smem.
// ---------------------------------------------------------------------------
#define GC_SMEM_FLOATS (16384 + 16384 + 576 + 576)
#define GC_SMEM_BYTES  (GC_SMEM_FLOATS * 4)

__global__ __launch_bounds__(256, 1) void gconv_kernel(
    const float* __restrict__ A, const float* __restrict__ X,
    const float* __restrict__ Wrel, const float* __restrict__ Wroot,
    const float* __restrict__ bias, float* __restrict__ out, int do_relu)
{
    extern __shared__ float sm[];
    float* sWrel  = sm;                 // 128x128
    float* sWroot = sm + 16384;         // 128x128
    float* sA     = sm + 32768;         // 64 rows x 8 k, stride 9 (pad)
    float* sX     = sA + 576;

    int tid = threadIdx.x;

    // Load both weight matrices into smem (float4, coalesced)
    for (int i = tid; i < 4096; i += 256) {
        ((float4*)sWrel)[i]  = ((const float4*)Wrel)[i];
        ((float4*)sWroot)[i] = ((const float4*)Wroot)[i];
    }

    int rowBase = blockIdx.x * 64;
    int tx = tid & 31;   // -> 4 output cols
    int ty = tid >> 5;   // -> 8 rows strided by 8

    float4 acc[8];
#pragma unroll
    for (int r = 0; r < 8; r++) acc[r] = make_float4(0.f, 0.f, 0.f, 0.f);

    // A/X staging: thread -> (row 0..63, float2 chunk 0..3)
    int lrow = tid >> 2;
    int kp   = tid & 3;
    int grow = rowBase + lrow;
    bool valid = (grow < NN);

#pragma unroll 1
    for (int kc = 0; kc < 16; kc++) {
        __syncthreads();   // also covers weight load on first iteration
        float2 va = make_float2(0.f, 0.f), vx = make_float2(0.f, 0.f);
        if (valid) {
            va = *(const float2*)&A[(size_t)grow * FC + kc * 8 + kp * 2];
            vx = *(const float2*)&X[(size_t)grow * FC + kc * 8 + kp * 2];
        }
        sA[lrow * 9 + kp * 2]     = va.x;
        sA[lrow * 9 + kp * 2 + 1] = va.y;
        sX[lrow * 9 + kp * 2]     = vx.x;
        sX[lrow * 9 + kp * 2 + 1] = vx.y;
        __syncthreads();

#pragma unroll
        for (int j = 0; j < 8; j++) {
            int k = kc * 8 + j;
            float4 wr = *(float4*)&sWrel [k * FC + tx * 4];
            float4 wt = *(float4*)&sWroot[k * FC + tx * 4];
#pragma unroll
            for (int r = 0; r < 8; r++) {
                float a  = sA[(ty + r * 8) * 9 + j];
                float xv = sX[(ty + r * 8) * 9 + j];
                acc[r].x += a * wr.x + xv * wt.x;
                acc[r].y += a * wr.y + xv * wt.y;
                acc[r].z += a * wr.z + xv * wt.z;
                acc[r].w += a * wr.w + xv * wt.w;
            }
        }
    }

    float4 bv = *(const float4*)&bias[tx * 4];
#pragma unroll
    for (int r = 0; r < 8; r++) {
        int row = rowBase + ty + r * 8;
        if (row < NN) {
            float4 o;
            o.x = acc[r].x + bv.x;
            o.y = acc[r].y + bv.y;
            o.z = acc[r].z + bv.z;
            o.w = acc[r].w + bv.w;
            if (do_relu) {
                o.x = fmaxf(o.x, 0.f); o.y = fmaxf(o.y, 0.f);
                o.z = fmaxf(o.z, 0.f); o.w = fmaxf(o.w, 0.f);
            }
            *(float4*)&out[(size_t)row * FC + tx * 4] = o;
        }
    }
}

// ---------------------------------------------------------------------------
// Mean-pool scatter: pool[batch[n]] += h[n], cnt[batch[n]] += 1
// Block = 256 threads = 8 nodes.
// ---------------------------------------------------------------------------
__global__ void pool_kernel(const float4* __restrict__ h,
                            const void* __restrict__ batch,
                            float4* __restrict__ pool, float* __restrict__ cnt)
{
    int n = blockIdx.x * 8 + (threadIdx.x >> 5);
    if (n >= NN) return;
    int c = threadIdx.x & 31;
    long long g = load_idx(batch, n, g_is64);
    float4 v = h[(long long)n * 32 + c];
    float4* p = pool + g * 32 + c;
    asm volatile("red.global.add.v4.f32 [%0], {%1,%2,%3,%4};"
                 :: "l"(p), "f"(v.x), "f"(v.y), "f"(v.z), "f"(v.w)
                 : "memory");
    if (c == 0) atomicAdd(&cnt[g], 1.0f);
}

// ---------------------------------------------------------------------------
// Final: out[g] = (pool[g] / max(cnt,1)) @ W_lin + b_lin    (512 x 10)
// ---------------------------------------------------------------------------
__global__ void final_kernel(const float* __restrict__ pool,
                             const float* __restrict__ cnt,
                             const float* __restrict__ Wlin,
                             const float* __restrict__ blin,
                             float* __restrict__ out)
{
    __shared__ float sp[FC];
    int g = blockIdx.x;
    int t = threadIdx.x;  // 128 threads
    float inv = 1.0f / fmaxf(cnt[g], 1.0f);
    sp[t] = pool[g * FC + t] * inv;
    __syncthreads();
    if (t < NOUT) {
        float s = blin[t];
#pragma unroll 16
        for (int k = 0; k < FC; k++)
            s += sp[k] * Wlin[k * NOUT + t];
        out[g * NOUT + t] = s;
    }
}

// ---------------------------------------------------------------------------
extern "C" void kernel_launch(void* const* d_in, const int* in_sizes, int n_in,
                              void* d_out, int out_size)
{
    const float* x     = (const float*)d_in[0];
    const void*  ei    = d_in[1];
    const void*  batch = d_in[2];
    const float* W1r = (const float*)d_in[3];
    const float* b1  = (const float*)d_in[4];
    const float* W1s = (const float*)d_in[5];
    const float* W2r = (const float*)d_in[6];
    const float* b2  = (const float*)d_in[7];
    const float* W2s = (const float*)d_in[8];
    const float* W3r = (const float*)d_in[9];
    const float* b3  = (const float*)d_in[10];
    const float* W3s = (const float*)d_in[11];
    const float* Wl  = (const float*)d_in[12];
    const float* bl  = (const float*)d_in[13];
    float* out = (float*)d_out;

    cudaFuncSetAttribute(gconv_kernel,
                         cudaFuncAttributeMaxDynamicSharedMemorySize,
                         GC_SMEM_BYTES);

    float4 *agg, *ha, *hb, *pool;
    float *cnt;
    cudaGetSymbolAddress((void**)&agg,  g_agg);
    cudaGetSymbolAddress((void**)&ha,   g_ha);
    cudaGetSymbolAddress((void**)&hb,   g_hb);
    cudaGetSymbolAddress((void**)&pool, g_pool);
    cudaGetSymbolAddress((void**)&cnt,  g_cnt);

    const int sblocks = (NE + 7) / 8;
    const int gblocks = (NN + 63) / 64;
    const int pblocks = (NN + 7) / 8;
    const size_t featBytes = (size_t)NN * FC * sizeof(float);

    // Determine index dtype (int32 vs int64) from the data itself.
    detect_kernel<<<1, 512>>>((const long long*)ei);

    // Layer 1
    cudaMemsetAsync(agg, 0, featBytes);
    scatter_kernel<<<sblocks, 256>>>((const float4*)x, ei, agg);
    gconv_kernel<<<gblocks, 256, GC_SMEM_BYTES>>>((const float*)agg, x,
                                                  W1r, W1s, b1, (float*)ha, 1);

    // Layer 2
    cudaMemsetAsync(agg, 0, featBytes);
    scatter_kernel<<<sblocks, 256>>>(ha, ei, agg);
    gconv_kernel<<<gblocks, 256, GC_SMEM_BYTES>>>((const float*)agg, (const float*)ha,
                                                  W2r, W2s, b2, (float*)hb, 1);

    // Layer 3 (no relu)
    cudaMemsetAsync(agg, 0, featBytes);
    scatter_kernel<<<sblocks, 256>>>(hb, ei, agg);
    gconv_kernel<<<gblocks, 256, GC_SMEM_BYTES>>>((const float*)agg, (const float*)hb,
                                                  W3r, W3s, b3, (float*)ha, 0);

    // Global mean pool + classifier
    cudaMemsetAsync(pool, 0, (size_t)NG * FC * sizeof(float));
    cudaMemsetAsync(cnt,  0, (size_t)NG * sizeof(float));
    pool_kernel<<<pblocks, 256>>>(ha, batch, pool, cnt);
    final_kernel<<<NG, FC>>>((const float*)pool, cnt, Wl, bl, out);
}

// round 5
// speedup vs baseline: 1.0505x; 1.0505x over previous
#include <cuda_runtime.h>

#define NN   100000
#define FC   128
#define NE   1600000
#define NG   512
#define NOUT 10

// Scratch (device globals; float4 => guaranteed 16B alignment for red.v4)
__device__ float4 g_agg [(size_t)NN * (FC / 4)];
__device__ float4 g_ha  [(size_t)NN * (FC / 4)];
__device__ float4 g_hb  [(size_t)NN * (FC / 4)];
__device__ float4 g_pool[NG * (FC / 4)];
__device__ float  g_cnt [NG];
__device__ int    g_is64;

// ---------------------------------------------------------------------------
// Index dtype detection: if the first 512 int64-interpreted values of
// edge_index are all in [0, NN), the buffer is int64; otherwise int32.
// ---------------------------------------------------------------------------
__global__ void detect_kernel(const long long* __restrict__ ei)
{
    __shared__ int ok;
    if (threadIdx.x == 0) ok = 1;
    __syncthreads();
    long long v = ei[threadIdx.x];           // 512 threads
    if (v < 0 || v >= NN) atomicAnd(&ok, 0);
    __syncthreads();
    if (threadIdx.x == 0) g_is64 = ok;
}

__device__ __forceinline__ long long load_idx(const void* base, int i, int is64)
{
    if (is64) return ((const long long*)base)[i];
    return (long long)((const int*)base)[i];
}

// ---------------------------------------------------------------------------
// Edge scatter-add: agg[dst] += x[src]. One warp per edge, one float4 per lane.
// Block = 256 threads = 8 edges.
// ---------------------------------------------------------------------------
__global__ void scatter_kernel(const float4* __restrict__ x,
                               const void* __restrict__ ei,
                               float4* __restrict__ agg)
{
    int e = blockIdx.x * 8 + (threadIdx.x >> 5);
    if (e >= NE) return;
    int c = threadIdx.x & 31;
    int is64 = g_is64;
    long long s = load_idx(ei, e, is64);
    long long d = load_idx(ei, e + NE, is64);   // dst = second row of [2, NE]
    float4 v = x[s * 32 + c];
    float4* p = agg + d * 32 + c;
    asm volatile("red.global.add.v4.f32 [%0], {%1,%2,%3,%4};"
                 :: "l"(p), "f"(v.x), "f"(v.y), "f"(v.z), "f"(v.w)
                 : "memory");
}

// ---------------------------------------------------------------------------
// Fused GraphConv GEMM: out = (relu?)(A @ Wrel + X @ Wroot + b)
// Block: 512 threads, 128 rows x 128 cols tile. Both weights resident in smem.
// 16 warps/SM for latency hiding (was 8 -> issue-limited).
// ---------------------------------------------------------------------------
#define GC_ROWS        128
#define GC_STG         (GC_ROWS * 9)     // staging: 128 rows x 8 k, stride 9
#define GC_SMEM_FLOATS (16384 + 16384 + GC_STG + GC_STG)
#define GC_SMEM_BYTES  (GC_SMEM_FLOATS * 4)

__global__ __launch_bounds__(512, 1) void gconv_kernel(
    const float* __restrict__ A, const float* __restrict__ X,
    const float* __restrict__ Wrel, const float* __restrict__ Wroot,
    const float* __restrict__ bias, float* __restrict__ out, int do_relu)
{
    extern __shared__ float sm[];
    float* sWrel  = sm;                 // 128x128
    float* sWroot = sm + 16384;         // 128x128
    float* sA     = sm + 32768;
    float* sX     = sA + GC_STG;

    int tid = threadIdx.x;

    // Load both weight matrices into smem (float4, coalesced)
    for (int i = tid; i < 4096; i += 512) {
        ((float4*)sWrel)[i]  = ((const float4*)Wrel)[i];
        ((float4*)sWroot)[i] = ((const float4*)Wroot)[i];
    }

    int rowBase = blockIdx.x * GC_ROWS;
    int tx = tid & 31;   // -> 4 output cols (tx*4 .. tx*4+3)
    int ty = tid >> 5;   // warp 0..15 -> 8 rows strided by 16

    float4 acc[8];
#pragma unroll
    for (int r = 0; r < 8; r++) acc[r] = make_float4(0.f, 0.f, 0.f, 0.f);

    // A/X staging: thread -> (row 0..127, float2 chunk 0..3)
    int lrow = tid >> 2;
    int kp   = tid & 3;
    int grow = rowBase + lrow;
    bool valid = (grow < NN);

#pragma unroll 1
    for (int kc = 0; kc < 16; kc++) {
        __syncthreads();   // also covers weight load on first iteration
        float2 va = make_float2(0.f, 0.f), vx = make_float2(0.f, 0.f);
        if (valid) {
            va = *(const float2*)&A[(size_t)grow * FC + kc * 8 + kp * 2];
            vx = *(const float2*)&X[(size_t)grow * FC + kc * 8 + kp * 2];
        }
        sA[lrow * 9 + kp * 2]     = va.x;
        sA[lrow * 9 + kp * 2 + 1] = va.y;
        sX[lrow * 9 + kp * 2]     = vx.x;
        sX[lrow * 9 + kp * 2 + 1] = vx.y;
        __syncthreads();

#pragma unroll
        for (int j = 0; j < 8; j++) {
            int k = kc * 8 + j;
            float4 wr = *(float4*)&sWrel [k * FC + tx * 4];
            float4 wt = *(float4*)&sWroot[k * FC + tx * 4];
#pragma unroll
            for (int r = 0; r < 8; r++) {
                float a  = sA[(ty + r * 16) * 9 + j];   // broadcast within warp
                float xv = sX[(ty + r * 16) * 9 + j];
                acc[r].x += a * wr.x + xv * wt.x;
                acc[r].y += a * wr.y + xv * wt.y;
                acc[r].z += a * wr.z + xv * wt.z;
                acc[r].w += a * wr.w + xv * wt.w;
            }
        }
    }

    float4 bv = *(const float4*)&bias[tx * 4];
#pragma unroll
    for (int r = 0; r < 8; r++) {
        int row = rowBase + ty + r * 16;
        if (row < NN) {
            float4 o;
            o.x = acc[r].x + bv.x;
            o.y = acc[r].y + bv.y;
            o.z = acc[r].z + bv.z;
            o.w = acc[r].w + bv.w;
            if (do_relu) {
                o.x = fmaxf(o.x, 0.f); o.y = fmaxf(o.y, 0.f);
                o.z = fmaxf(o.z, 0.f); o.w = fmaxf(o.w, 0.f);
            }
            *(float4*)&out[(size_t)row * FC + tx * 4] = o;
        }
    }
}

// ---------------------------------------------------------------------------
// Mean-pool scatter: pool[batch[n]] += h[n], cnt[batch[n]] += 1
// Block = 256 threads = 8 nodes.
// ---------------------------------------------------------------------------
__global__ void pool_kernel(const float4* __restrict__ h,
                            const void* __restrict__ batch,
                            float4* __restrict__ pool, float* __restrict__ cnt)
{
    int n = blockIdx.x * 8 + (threadIdx.x >> 5);
    if (n >= NN) return;
    int c = threadIdx.x & 31;
    long long g = load_idx(batch, n, g_is64);
    float4 v = h[(long long)n * 32 + c];
    float4* p = pool + g * 32 + c;
    asm volatile("red.global.add.v4.f32 [%0], {%1,%2,%3,%4};"
                 :: "l"(p), "f"(v.x), "f"(v.y), "f"(v.z), "f"(v.w)
                 : "memory");
    if (c == 0) atomicAdd(&cnt[g], 1.0f);
}

// ---------------------------------------------------------------------------
// Final: out[g] = (pool[g] / max(cnt,1)) @ W_lin + b_lin    (512 x 10)
// ---------------------------------------------------------------------------
__global__ void final_kernel(const float* __restrict__ pool,
                             const float* __restrict__ cnt,
                             const float* __restrict__ Wlin,
                             const float* __restrict__ blin,
                             float* __restrict__ out)
{
    __shared__ float sp[FC];
    int g = blockIdx.x;
    int t = threadIdx.x;  // 128 threads
    float inv = 1.0f / fmaxf(cnt[g], 1.0f);
    sp[t] = pool[g * FC + t] * inv;
    __syncthreads();
    if (t < NOUT) {
        float s = blin[t];
#pragma unroll 16
        for (int k = 0; k < FC; k++)
            s += sp[k] * Wlin[k * NOUT + t];
        out[g * NOUT + t] = s;
    }
}

// ---------------------------------------------------------------------------
extern "C" void kernel_launch(void* const* d_in, const int* in_sizes, int n_in,
                              void* d_out, int out_size)
{
    const float* x     = (const float*)d_in[0];
    const void*  ei    = d_in[1];
    const void*  batch = d_in[2];
    const float* W1r = (const float*)d_in[3];
    const float* b1  = (const float*)d_in[4];
    const float* W1s = (const float*)d_in[5];
    const float* W2r = (const float*)d_in[6];
    const float* b2  = (const float*)d_in[7];
    const float* W2s = (const float*)d_in[8];
    const float* W3r = (const float*)d_in[9];
    const float* b3  = (const float*)d_in[10];
    const float* W3s = (const float*)d_in[11];
    const float* Wl  = (const float*)d_in[12];
    const float* bl  = (const float*)d_in[13];
    float* out = (float*)d_out;

    cudaFuncSetAttribute(gconv_kernel,
                         cudaFuncAttributeMaxDynamicSharedMemorySize,
                         GC_SMEM_BYTES);

    float4 *agg, *ha, *hb, *pool;
    float *cnt;
    cudaGetSymbolAddress((void**)&agg,  g_agg);
    cudaGetSymbolAddress((void**)&ha,   g_ha);
    cudaGetSymbolAddress((void**)&hb,   g_hb);
    cudaGetSymbolAddress((void**)&pool, g_pool);
    cudaGetSymbolAddress((void**)&cnt,  g_cnt);

    const int sblocks = (NE + 7) / 8;
    const int gblocks = (NN + GC_ROWS - 1) / GC_ROWS;
    const int pblocks = (NN + 7) / 8;
    const size_t featBytes = (size_t)NN * FC * sizeof(float);

    // Determine index dtype (int32 vs int64) from the data itself.
    detect_kernel<<<1, 512>>>((const long long*)ei);

    // Layer 1
    cudaMemsetAsync(agg, 0, featBytes);
    scatter_kernel<<<sblocks, 256>>>((const float4*)x, ei, agg);
    gconv_kernel<<<gblocks, 512, GC_SMEM_BYTES>>>((const float*)agg, x,
                                                  W1r, W1s, b1, (float*)ha, 1);

    // Layer 2
    cudaMemsetAsync(agg, 0, featBytes);
    scatter_kernel<<<sblocks, 256>>>(ha, ei, agg);
    gconv_kernel<<<gblocks, 512, GC_SMEM_BYTES>>>((const float*)agg, (const float*)ha,
                                                  W2r, W2s, b2, (float*)hb, 1);

    // Layer 3 (no relu)
    cudaMemsetAsync(agg, 0, featBytes);
    scatter_kernel<<<sblocks, 256>>>(hb, ei, agg);
    gconv_kernel<<<gblocks, 512, GC_SMEM_BYTES>>>((const float*)agg, (const float*)hb,
                                                  W3r, W3s, b3, (float*)ha, 0);

    // Global mean pool + classifier
    cudaMemsetAsync(pool, 0, (size_t)NG * FC * sizeof(float));
    cudaMemsetAsync(cnt,  0, (size_t)NG * sizeof(float));
    pool_kernel<<<pblocks, 256>>>(ha, batch, pool, cnt);
    final_kernel<<<NG, FC>>>((const float*)pool, cnt, Wl, bl, out);
}

// round 6
// speedup vs baseline: 1.6582x; 1.5785x over previous
#include <cuda_runtime.h>
#include <cstdint>

#define NN   100000
#define FC   128
#define NE   1600000
#define NG   512
#define NOUT 10

// Scratch (device globals; float4 => guaranteed 16B alignment for red.v4)
__device__ float4 g_agg [(size_t)NN * (FC / 4)];
__device__ float4 g_ha  [(size_t)NN * (FC / 4)];
__device__ float4 g_hb  [(size_t)NN * (FC / 4)];
__device__ float4 g_pool[NG * (FC / 4)];
__device__ float  g_cnt [NG];
__device__ int    g_is64;

// ---------------------------------------------------------------------------
// Index dtype detection (int32 vs int64 edge/batch buffers)
// ---------------------------------------------------------------------------
__global__ void detect_kernel(const long long* __restrict__ ei)
{
    __shared__ int ok;
    if (threadIdx.x == 0) ok = 1;
    __syncthreads();
    long long v = ei[threadIdx.x];           // 512 threads
    if (v < 0 || v >= NN) atomicAnd(&ok, 0);
    __syncthreads();
    if (threadIdx.x == 0) g_is64 = ok;
}

__device__ __forceinline__ long long load_idx(const void* base, int i, int is64)
{
    if (is64) return ((const long long*)base)[i];
    return (long long)((const int*)base)[i];
}

// ---------------------------------------------------------------------------
// Edge scatter-add: agg[dst] += x[src]. One warp per edge, float4 per lane.
// ---------------------------------------------------------------------------
__global__ void scatter_kernel(const float4* __restrict__ x,
                               const void* __restrict__ ei,
                               float4* __restrict__ agg)
{
    int e = blockIdx.x * 8 + (threadIdx.x >> 5);
    if (e >= NE) return;
    int c = threadIdx.x & 31;
    int is64 = g_is64;
    long long s = load_idx(ei, e, is64);
    long long d = load_idx(ei, e + NE, is64);
    float4 v = x[s * 32 + c];
    float4* p = agg + d * 32 + c;
    asm volatile("red.global.add.v4.f32 [%0], {%1,%2,%3,%4};"
                 :: "l"(p), "f"(v.x), "f"(v.y), "f"(v.z), "f"(v.w)
                 : "memory");
}

// ---------------------------------------------------------------------------
// Tensor-core GraphConv: out = (relu?)([A|X] @ [Wrel;Wroot] + b)
//   Single GEMM, M=block of 128 rows, N=128, K=256, tf32 mma.m16n8k8.
//   Weights (256x128) resident in smem as tf32 bits, stride 136 (pad).
//   A staged in 32-k chunks, stride 36 (pad), register-prefetched.
// ---------------------------------------------------------------------------
#define WSTRIDE 136
#define ASTRIDE 36
#define SW_WORDS (256 * WSTRIDE)           // 34816
#define SA_WORDS (128 * ASTRIDE)           //  4608
#define GC_SMEM_BYTES ((SW_WORDS + SA_WORDS) * 4)

__device__ __forceinline__ uint32_t f2tf32(float f)
{
    uint32_t r;
    asm("cvt.rna.tf32.f32 %0, %1;" : "=r"(r) : "f"(f));
    return r;
}

__device__ __forceinline__ void mma_tf32(float c[4],
                                         uint32_t a0, uint32_t a1,
                                         uint32_t a2, uint32_t a3,
                                         uint32_t b0, uint32_t b1)
{
    asm volatile("mma.sync.aligned.m16n8k8.row.col.f32.tf32.tf32.f32 "
                 "{%0,%1,%2,%3}, {%4,%5,%6,%7}, {%8,%9}, {%0,%1,%2,%3};"
                 : "+f"(c[0]), "+f"(c[1]), "+f"(c[2]), "+f"(c[3])
                 : "r"(a0), "r"(a1), "r"(a2), "r"(a3), "r"(b0), "r"(b1));
}

__global__ __launch_bounds__(256, 1) void gconv_tc_kernel(
    const float* __restrict__ A, const float* __restrict__ X,
    const float* __restrict__ Wrel, const float* __restrict__ Wroot,
    const float* __restrict__ bias, float* __restrict__ out, int do_relu)
{
    extern __shared__ uint32_t smw[];
    uint32_t* sW = smw;               // 256 x 136 tf32 words
    uint32_t* sA = smw + SW_WORDS;    // 128 x 36  tf32 words

    const int tid  = threadIdx.x;
    const int warp = tid >> 5;
    const int lane = tid & 31;
    const int rowBase = blockIdx.x * 128;

    // ---- Stage stacked weights [Wrel ; Wroot] into smem as tf32 ----
    for (int i = tid; i < 8192; i += 256) {          // 8192 float4
        int k  = i >> 5;
        int n4 = i & 31;
        const float* src = (k < 128) ? &Wrel[k * FC + n4 * 4]
                                     : &Wroot[(k - 128) * FC + n4 * 4];
        float4 w = *(const float4*)src;
        uint32_t* d = &sW[k * WSTRIDE + n4 * 4];
        d[0] = f2tf32(w.x); d[1] = f2tf32(w.y);
        d[2] = f2tf32(w.z); d[3] = f2tf32(w.w);
    }

    // ---- Stage chunk 0 of activations ----
    // chunk c covers K [c*32, c*32+32); c<4 from A(agg), c>=4 from X.
    {
        for (int j = 0; j < 4; j++) {
            int idx = tid + j * 256;                 // 0..1023
            int row = idx >> 3;
            int f4c = idx & 7;
            float4 v = make_float4(0.f, 0.f, 0.f, 0.f);
            int grow = rowBase + row;
            if (grow < NN)
                v = *(const float4*)&A[(size_t)grow * FC + f4c * 4];
            uint32_t* d = &sA[row * ASTRIDE + f4c * 4];
            d[0] = f2tf32(v.x); d[1] = f2tf32(v.y);
            d[2] = f2tf32(v.z); d[3] = f2tf32(v.w);
        }
    }
    __syncthreads();

    float acc[16][4];
#pragma unroll
    for (int nt = 0; nt < 16; nt++)
#pragma unroll
        for (int q = 0; q < 4; q++) acc[nt][q] = 0.f;

    const int arow0 = (warp * 16 + (lane >> 2)) * ASTRIDE;
    const int arow1 = arow0 + 8 * ASTRIDE;
    const int bcol  = lane >> 2;
    const int ak    = lane & 3;

    float4 pf[4];
#pragma unroll 1
    for (int c = 0; c < 8; c++) {
        // prefetch next chunk into registers
        if (c < 7) {
            const float* srcM = (c + 1 < 4) ? A : X;
            int koff = ((c + 1) & 3) * 32;
#pragma unroll
            for (int j = 0; j < 4; j++) {
                int idx = tid + j * 256;
                int row = idx >> 3;
                int f4c = idx & 7;
                int grow = rowBase + row;
                pf[j] = (grow < NN)
                    ? *(const float4*)&srcM[(size_t)grow * FC + koff + f4c * 4]
                    : make_float4(0.f, 0.f, 0.f, 0.f);
            }
        }

        // compute 4 ksteps over this chunk
#pragma unroll
        for (int ks = 0; ks < 4; ks++) {
            int kl = ks * 8;
            uint32_t a0 = sA[arow0 + kl + ak];
            uint32_t a1 = sA[arow1 + kl + ak];
            uint32_t a2 = sA[arow0 + kl + ak + 4];
            uint32_t a3 = sA[arow1 + kl + ak + 4];
            int kg = c * 32 + kl;
            const uint32_t* b0p = &sW[(kg + ak) * WSTRIDE + bcol];
            const uint32_t* b1p = b0p + 4 * WSTRIDE;
#pragma unroll
            for (int nt = 0; nt < 16; nt++) {
                uint32_t b0 = b0p[nt * 8];
                uint32_t b1 = b1p[nt * 8];
                mma_tf32(acc[nt], a0, a1, a2, a3, b0, b1);
            }
        }
        __syncthreads();

        // commit prefetched chunk to smem
        if (c < 7) {
#pragma unroll
            for (int j = 0; j < 4; j++) {
                int idx = tid + j * 256;
                int row = idx >> 3;
                int f4c = idx & 7;
                uint32_t* d = &sA[row * ASTRIDE + f4c * 4];
                d[0] = f2tf32(pf[j].x); d[1] = f2tf32(pf[j].y);
                d[2] = f2tf32(pf[j].z); d[3] = f2tf32(pf[j].w);
            }
            __syncthreads();
        }
    }

    // ---- Epilogue: bias (+relu), write fp32 ----
    int r0 = rowBase + warp * 16 + (lane >> 2);
    int r1 = r0 + 8;
    int coff = (lane & 3) * 2;
#pragma unroll
    for (int nt = 0; nt < 16; nt++) {
        int col = nt * 8 + coff;
        float2 bb = *(const float2*)&bias[col];
        float2 o0, o1;
        o0.x = acc[nt][0] + bb.x; o0.y = acc[nt][1] + bb.y;
        o1.x = acc[nt][2] + bb.x; o1.y = acc[nt][3] + bb.y;
        if (do_relu) {
            o0.x = fmaxf(o0.x, 0.f); o0.y = fmaxf(o0.y, 0.f);
            o1.x = fmaxf(o1.x, 0.f); o1.y = fmaxf(o1.y, 0.f);
        }
        if (r0 < NN) *(float2*)&out[(size_t)r0 * FC + col] = o0;
        if (r1 < NN) *(float2*)&out[(size_t)r1 * FC + col] = o1;
    }
}

// ---------------------------------------------------------------------------
// Mean-pool scatter: pool[batch[n]] += h[n], cnt[batch[n]] += 1
// ---------------------------------------------------------------------------
__global__ void pool_kernel(const float4* __restrict__ h,
                            const void* __restrict__ batch,
                            float4* __restrict__ pool, float* __restrict__ cnt)
{
    int n = blockIdx.x * 8 + (threadIdx.x >> 5);
    if (n >= NN) return;
    int c = threadIdx.x & 31;
    long long g = load_idx(batch, n, g_is64);
    float4 v = h[(long long)n * 32 + c];
    float4* p = pool + g * 32 + c;
    asm volatile("red.global.add.v4.f32 [%0], {%1,%2,%3,%4};"
                 :: "l"(p), "f"(v.x), "f"(v.y), "f"(v.z), "f"(v.w)
                 : "memory");
    if (c == 0) atomicAdd(&cnt[g], 1.0f);
}

// ---------------------------------------------------------------------------
// Final: out[g] = (pool[g] / max(cnt,1)) @ W_lin + b_lin    (512 x 10)
// ---------------------------------------------------------------------------
__global__ void final_kernel(const float* __restrict__ pool,
                             const float* __restrict__ cnt,
                             const float* __restrict__ Wlin,
                             const float* __restrict__ blin,
                             float* __restrict__ out)
{
    __shared__ float sp[FC];
    int g = blockIdx.x;
    int t = threadIdx.x;  // 128 threads
    float inv = 1.0f / fmaxf(cnt[g], 1.0f);
    sp[t] = pool[g * FC + t] * inv;
    __syncthreads();
    if (t < NOUT) {
        float s = blin[t];
#pragma unroll 16
        for (int k = 0; k < FC; k++)
            s += sp[k] * Wlin[k * NOUT + t];
        out[g * NOUT + t] = s;
    }
}

// ---------------------------------------------------------------------------
extern "C" void kernel_launch(void* const* d_in, const int* in_sizes, int n_in,
                              void* d_out, int out_size)
{
    const float* x     = (const float*)d_in[0];
    const void*  ei    = d_in[1];
    const void*  batch = d_in[2];
    const float* W1r = (const float*)d_in[3];
    const float* b1  = (const float*)d_in[4];
    const float* W1s = (const float*)d_in[5];
    const float* W2r = (const float*)d_in[6];
    const float* b2  = (const float*)d_in[7];
    const float* W2s = (const float*)d_in[8];
    const float* W3r = (const float*)d_in[9];
    const float* b3  = (const float*)d_in[10];
    const float* W3s = (const float*)d_in[11];
    const float* Wl  = (const float*)d_in[12];
    const float* bl  = (const float*)d_in[13];
    float* out = (float*)d_out;

    cudaFuncSetAttribute(gconv_tc_kernel,
                         cudaFuncAttributeMaxDynamicSharedMemorySize,
                         GC_SMEM_BYTES);

    float4 *agg, *ha, *hb, *pool;
    float *cnt;
    cudaGetSymbolAddress((void**)&agg,  g_agg);
    cudaGetSymbolAddress((void**)&ha,   g_ha);
    cudaGetSymbolAddress((void**)&hb,   g_hb);
    cudaGetSymbolAddress((void**)&pool, g_pool);
    cudaGetSymbolAddress((void**)&cnt,  g_cnt);

    const int sblocks = (NE + 7) / 8;
    const int gblocks = (NN + 127) / 128;
    const int pblocks = (NN + 7) / 8;
    const size_t featBytes = (size_t)NN * FC * sizeof(float);

    detect_kernel<<<1, 512>>>((const long long*)ei);

    // Layer 1
    cudaMemsetAsync(agg, 0, featBytes);
    scatter_kernel<<<sblocks, 256>>>((const float4*)x, ei, agg);
    gconv_tc_kernel<<<gblocks, 256, GC_SMEM_BYTES>>>((const float*)agg, x,
                                                     W1r, W1s, b1, (float*)ha, 1);

    // Layer 2
    cudaMemsetAsync(agg, 0, featBytes);
    scatter_kernel<<<sblocks, 256>>>(ha, ei, agg);
    gconv_tc_kernel<<<gblocks, 256, GC_SMEM_BYTES>>>((const float*)agg, (const float*)ha,
                                                     W2r, W2s, b2, (float*)hb, 1);

    // Layer 3 (no relu)
    cudaMemsetAsync(agg, 0, featBytes);
    scatter_kernel<<<sblocks, 256>>>(hb, ei, agg);
    gconv_tc_kernel<<<gblocks, 256, GC_SMEM_BYTES>>>((const float*)agg, (const float*)hb,
                                                     W3r, W3s, b3, (float*)ha, 0);

    // Global mean pool + classifier
    cudaMemsetAsync(pool, 0, (size_t)NG * FC * sizeof(float));
    cudaMemsetAsync(cnt,  0, (size_t)NG * sizeof(float));
    pool_kernel<<<pblocks, 256>>>(ha, batch, pool, cnt);
    final_kernel<<<NG, FC>>>((const float*)pool, cnt, Wl, bl, out);
}

// round 8
// speedup vs baseline: 3.0999x; 1.8694x over previous
#include <cuda_runtime.h>
#include <cstdint>

#define NN   100000
#define FC   128
#define NE   1600000
#define NG   512
#define NOUT 10
#define NSCAN (NN + 1)
#define SCAN_BLK 1024
#define NBLK ((NSCAN + SCAN_BLK - 1) / SCAN_BLK)   // 98

// Scratch (device globals)
__device__ float4 g_agg [(size_t)NN * (FC / 4)];
__device__ float4 g_ha  [(size_t)NN * (FC / 4)];
__device__ float4 g_hb  [(size_t)NN * (FC / 4)];
__device__ int    g_rowptr[NSCAN];
__device__ int    g_cursor[NN];
__device__ int    g_esrc[NE];
__device__ int    g_part[NBLK];
__device__ int    g_is64;

// ---------------------------------------------------------------------------
// Index dtype detection (int32 vs int64 edge/batch buffers)
// ---------------------------------------------------------------------------
__global__ void detect_kernel(const long long* __restrict__ ei)
{
    __shared__ int ok;
    if (threadIdx.x == 0) ok = 1;
    __syncthreads();
    long long v = ei[threadIdx.x];           // 512 threads
    if (v < 0 || v >= NN) atomicAnd(&ok, 0);
    __syncthreads();
    if (threadIdx.x == 0) g_is64 = ok;
}

__device__ __forceinline__ long long load_idx(const void* base, int i, int is64)
{
    if (is64) return ((const long long*)base)[i];
    return (long long)((const int*)base)[i];
}

// ---------------------------------------------------------------------------
// CSR build: histogram -> scan -> fill
// ---------------------------------------------------------------------------
__global__ void hist_kernel(const void* __restrict__ ei, int* __restrict__ deg)
{
    int is64 = g_is64;
    for (int e = blockIdx.x * blockDim.x + threadIdx.x; e < NE;
         e += gridDim.x * blockDim.x) {
        int d = (int)load_idx(ei, e + NE, is64);
        atomicAdd(&deg[d + 1], 1);
    }
}

__global__ void scanA_kernel(int* __restrict__ deg, int* __restrict__ part)
{
    __shared__ int sm[SCAN_BLK];
    int tid = threadIdx.x;
    int i = blockIdx.x * SCAN_BLK + tid;
    int v = (i < NSCAN) ? deg[i] : 0;
    sm[tid] = v;
    __syncthreads();
#pragma unroll
    for (int off = 1; off < SCAN_BLK; off <<= 1) {
        int t = (tid >= off) ? sm[tid - off] : 0;
        __syncthreads();
        sm[tid] += t;
        __syncthreads();
    }
    if (i < NSCAN) deg[i] = sm[tid];
    if (tid == SCAN_BLK - 1) part[blockIdx.x] = sm[tid];
}

__global__ void scanB_kernel(int* __restrict__ part)
{
    __shared__ int sm[128];
    int tid = threadIdx.x;   // 128 >= NBLK
    sm[tid] = (tid < NBLK) ? part[tid] : 0;
    __syncthreads();
#pragma unroll
    for (int off = 1; off < 128; off <<= 1) {
        int t = (tid >= off) ? sm[tid - off] : 0;
        __syncthreads();
        sm[tid] += t;
        __syncthreads();
    }
    if (tid < NBLK) part[tid] = sm[tid];
}

__global__ void scanC_kernel(int* __restrict__ deg, const int* __restrict__ part,
                             int* __restrict__ cursor)
{
    int i = blockIdx.x * SCAN_BLK + threadIdx.x;
    if (i < NSCAN) {
        int v = deg[i];
        if (blockIdx.x > 0) v += part[blockIdx.x - 1];
        deg[i] = v;
        if (i < NN) cursor[i] = v;   // cursor starts at rowptr[n]
    }
}

__global__ void fill_kernel(const void* __restrict__ ei,
                            int* __restrict__ cursor, int* __restrict__ esrc)
{
    int is64 = g_is64;
    for (int e = blockIdx.x * blockDim.x + threadIdx.x; e < NE;
         e += gridDim.x * blockDim.x) {
        int s = (int)load_idx(ei, e, is64);
        int d = (int)load_idx(ei, e + NE, is64);
        int pos = atomicAdd(&cursor[d], 1);
        esrc[pos] = s;
    }
}

// ---------------------------------------------------------------------------
// Atomic-free gather: agg[n] = sum_{j in row n} x[esrc[j]]
// One warp per node, float4 per lane, dual accumulators for MLP.
// ---------------------------------------------------------------------------
__global__ void gather_kernel(const float4* __restrict__ x,
                              const int* __restrict__ rowptr,
                              const int* __restrict__ esrc,
                              float4* __restrict__ agg)
{
    int n = blockIdx.x * 8 + (threadIdx.x >> 5);
    if (n >= NN) return;
    int c = threadIdx.x & 31;
    int lo = __ldg(&rowptr[n]);
    int hi = __ldg(&rowptr[n + 1]);
    float4 a0 = make_float4(0.f, 0.f, 0.f, 0.f);
    float4 a1 = make_float4(0.f, 0.f, 0.f, 0.f);
    int j = lo;
    for (; j + 1 < hi; j += 2) {
        int s0 = __ldg(&esrc[j]);
        int s1 = __ldg(&esrc[j + 1]);
        float4 v0 = x[(long long)s0 * 32 + c];
        float4 v1 = x[(long long)s1 * 32 + c];
        a0.x += v0.x; a0.y += v0.y; a0.z += v0.z; a0.w += v0.w;
        a1.x += v1.x; a1.y += v1.y; a1.z += v1.z; a1.w += v1.w;
    }
    if (j < hi) {
        int s0 = __ldg(&esrc[j]);
        float4 v0 = x[(long long)s0 * 32 + c];
        a0.x += v0.x; a0.y += v0.y; a0.z += v0.z; a0.w += v0.w;
    }
    a0.x += a1.x; a0.y += a1.y; a0.z += a1.z; a0.w += a1.w;
    agg[(long long)n * 32 + c] = a0;
}

// ---------------------------------------------------------------------------
// Tensor-core GraphConv: out = (relu?)([A|X] @ [Wrel;Wroot] + b)
//   Single GEMM, M=128 rows/block, N=128, K=256, tf32 mma.m16n8k8.
// ---------------------------------------------------------------------------
#define WSTRIDE 136
#define ASTRIDE 36
#define SW_WORDS (256 * WSTRIDE)
#define SA_WORDS (128 * ASTRIDE)
#define GC_SMEM_BYTES ((SW_WORDS + SA_WORDS) * 4)

__device__ __forceinline__ uint32_t f2tf32(float f)
{
    uint32_t r;
    asm("cvt.rna.tf32.f32 %0, %1;" : "=r"(r) : "f"(f));
    return r;
}

__device__ __forceinline__ void mma_tf32(float c[4],
                                         uint32_t a0, uint32_t a1,
                                         uint32_t a2, uint32_t a3,
                                         uint32_t b0, uint32_t b1)
{
    asm volatile("mma.sync.aligned.m16n8k8.row.col.f32.tf32.tf32.f32 "
                 "{%0,%1,%2,%3}, {%4,%5,%6,%7}, {%8,%9}, {%0,%1,%2,%3};"
                 : "+f"(c[0]), "+f"(c[1]), "+f"(c[2]), "+f"(c[3])
                 : "r"(a0), "r"(a1), "r"(a2), "r"(a3), "r"(b0), "r"(b1));
}

__global__ __launch_bounds__(256, 1) void gconv_tc_kernel(
    const float* __restrict__ A, const float* __restrict__ X,
    const float* __restrict__ Wrel, const float* __restrict__ Wroot,
    const float* __restrict__ bias, float* __restrict__ out, int do_relu)
{
    extern __shared__ uint32_t smw[];
    uint32_t* sW = smw;               // 256 x 136 tf32 words
    uint32_t* sA = smw + SW_WORDS;    // 128 x 36  tf32 words

    const int tid  = threadIdx.x;
    const int warp = tid >> 5;
    const int lane = tid & 31;
    const int rowBase = blockIdx.x * 128;

    for (int i = tid; i < 8192; i += 256) {
        int k  = i >> 5;
        int n4 = i & 31;
        const float* src = (k < 128) ? &Wrel[k * FC + n4 * 4]
                                     : &Wroot[(k - 128) * FC + n4 * 4];
        float4 w = *(const float4*)src;
        uint32_t* d = &sW[k * WSTRIDE + n4 * 4];
        d[0] = f2tf32(w.x); d[1] = f2tf32(w.y);
        d[2] = f2tf32(w.z); d[3] = f2tf32(w.w);
    }

    {
        for (int j = 0; j < 4; j++) {
            int idx = tid + j * 256;
            int row = idx >> 3;
            int f4c = idx & 7;
            float4 v = make_float4(0.f, 0.f, 0.f, 0.f);
            int grow = rowBase + row;
            if (grow < NN)
                v = *(const float4*)&A[(size_t)grow * FC + f4c * 4];
            uint32_t* d = &sA[row * ASTRIDE + f4c * 4];
            d[0] = f2tf32(v.x); d[1] = f2tf32(v.y);
            d[2] = f2tf32(v.z); d[3] = f2tf32(v.w);
        }
    }
    __syncthreads();

    float acc[16][4];
#pragma unroll
    for (int nt = 0; nt < 16; nt++)
#pragma unroll
        for (int q = 0; q < 4; q++) acc[nt][q] = 0.f;

    const int arow0 = (warp * 16 + (lane >> 2)) * ASTRIDE;
    const int arow1 = arow0 + 8 * ASTRIDE;
    const int bcol  = lane >> 2;
    const int ak    = lane & 3;

    float4 pf[4];
#pragma unroll 1
    for (int c = 0; c < 8; c++) {
        if (c < 7) {
            const float* srcM = (c + 1 < 4) ? A : X;
            int koff = ((c + 1) & 3) * 32;
#pragma unroll
            for (int j = 0; j < 4; j++) {
                int idx = tid + j * 256;
                int row = idx >> 3;
                int f4c = idx & 7;
                int grow = rowBase + row;
                pf[j] = (grow < NN)
                    ? *(const float4*)&srcM[(size_t)grow * FC + koff + f4c * 4]
                    : make_float4(0.f, 0.f, 0.f, 0.f);
            }
        }

#pragma unroll
        for (int ks = 0; ks < 4; ks++) {
            int kl = ks * 8;
            uint32_t a0 = sA[arow0 + kl + ak];
            uint32_t a1 = sA[arow1 + kl + ak];
            uint32_t a2 = sA[arow0 + kl + ak + 4];
            uint32_t a3 = sA[arow1 + kl + ak + 4];
            int kg = c * 32 + kl;
            const uint32_t* b0p = &sW[(kg + ak) * WSTRIDE + bcol];
            const uint32_t* b1p = b0p + 4 * WSTRIDE;
#pragma unroll
            for (int nt = 0; nt < 16; nt++) {
                uint32_t b0 = b0p[nt * 8];
                uint32_t b1 = b1p[nt * 8];
                mma_tf32(acc[nt], a0, a1, a2, a3, b0, b1);
            }
        }
        __syncthreads();

        if (c < 7) {
#pragma unroll
            for (int j = 0; j < 4; j++) {
                int idx = tid + j * 256;
                int row = idx >> 3;
                int f4c = idx & 7;
                uint32_t* d = &sA[row * ASTRIDE + f4c * 4];
                d[0] = f2tf32(pf[j].x); d[1] = f2tf32(pf[j].y);
                d[2] = f2tf32(pf[j].z); d[3] = f2tf32(pf[j].w);
            }
            __syncthreads();
        }
    }

    int r0 = rowBase + warp * 16 + (lane >> 2);
    int r1 = r0 + 8;
    int coff = (lane & 3) * 2;
#pragma unroll
    for (int nt = 0; nt < 16; nt++) {
        int col = nt * 8 + coff;
        float2 bb = *(const float2*)&bias[col];
        float2 o0, o1;
        o0.x = acc[nt][0] + bb.x; o0.y = acc[nt][1] + bb.y;
        o1.x = acc[nt][2] + bb.x; o1.y = acc[nt][3] + bb.y;
        if (do_relu) {
            o0.x = fmaxf(o0.x, 0.f); o0.y = fmaxf(o0.y, 0.f);
            o1.x = fmaxf(o1.x, 0.f); o1.y = fmaxf(o1.y, 0.f);
        }
        if (r0 < NN) *(float2*)&out[(size_t)r0 * FC + col] = o0;
        if (r1 < NN) *(float2*)&out[(size_t)r1 * FC + col] = o1;
    }
}

// ---------------------------------------------------------------------------
// Fused mean-pool + classifier. batch is sorted => graph g owns contiguous
// node range found by binary search. One block (128 thr) per graph.
// ---------------------------------------------------------------------------
__global__ void poolfinal_kernel(const float* __restrict__ h,
                                 const void* __restrict__ batch,
                                 const float* __restrict__ Wlin,
                                 const float* __restrict__ blin,
                                 float* __restrict__ out)
{
    __shared__ float sp[FC];
    __shared__ int bounds[2];
    int g = blockIdx.x;
    int t = threadIdx.x;
    int is64 = g_is64;

    if (t < 2) {
        // t=0: first n with batch[n] >= g ; t=1: first n with batch[n] >= g+1
        long long target = g + t;
        int lo = 0, hi = NN;
        while (lo < hi) {
            int mid = (lo + hi) >> 1;
            if (load_idx(batch, mid, is64) < target) lo = mid + 1;
            else hi = mid;
        }
        bounds[t] = lo;
    }
    __syncthreads();
    int lo = bounds[0], hi = bounds[1];

    float s = 0.f;
    for (int n = lo; n < hi; n++)
        s += h[(size_t)n * FC + t];
    float inv = 1.0f / fmaxf((float)(hi - lo), 1.0f);
    sp[t] = s * inv;
    __syncthreads();

    if (t < NOUT) {
        float acc = blin[t];
#pragma unroll 16
        for (int k = 0; k < FC; k++)
            acc += sp[k] * Wlin[k * NOUT + t];
        out[g * NOUT + t] = acc;
    }
}

// ---------------------------------------------------------------------------
extern "C" void kernel_launch(void* const* d_in, const int* in_sizes, int n_in,
                              void* d_out, int out_size)
{
    const float* x     = (const float*)d_in[0];
    const void*  ei    = d_in[1];
    const void*  batch = d_in[2];
    const float* W1r = (const float*)d_in[3];
    const float* b1  = (const float*)d_in[4];
    const float* W1s = (const float*)d_in[5];
    const float* W2r = (const float*)d_in[6];
    const float* b2  = (const float*)d_in[7];
    const float* W2s = (const float*)d_in[8];
    const float* W3r = (const float*)d_in[9];
    const float* b3  = (const float*)d_in[10];
    const float* W3s = (const float*)d_in[11];
    const float* Wl  = (const float*)d_in[12];
    const float* bl  = (const float*)d_in[13];
    float* out = (float*)d_out;

    cudaFuncSetAttribute(gconv_tc_kernel,
                         cudaFuncAttributeMaxDynamicSharedMemorySize,
                         GC_SMEM_BYTES);

    float4 *agg, *ha, *hb;
    int *rowptr, *cursor, *esrc, *part;
    cudaGetSymbolAddress((void**)&agg,    g_agg);
    cudaGetSymbolAddress((void**)&ha,     g_ha);
    cudaGetSymbolAddress((void**)&hb,     g_hb);
    cudaGetSymbolAddress((void**)&rowptr, g_rowptr);
    cudaGetSymbolAddress((void**)&cursor, g_cursor);
    cudaGetSymbolAddress((void**)&esrc,   g_esrc);
    cudaGetSymbolAddress((void**)&part,   g_part);

    const int nblocks8 = (NN + 7) / 8;           // gather: warp/node
    const int gblocks  = (NN + 127) / 128;

    detect_kernel<<<1, 512>>>((const long long*)ei);

    // ---- CSR build (once, reused by all 3 layers) ----
    cudaMemsetAsync(rowptr, 0, NSCAN * sizeof(int));
    hist_kernel<<<2048, 256>>>(ei, rowptr);
    scanA_kernel<<<NBLK, SCAN_BLK>>>(rowptr, part);
    scanB_kernel<<<1, 128>>>(part);
    scanC_kernel<<<NBLK, SCAN_BLK>>>(rowptr, part, cursor);
    fill_kernel<<<2048, 256>>>(ei, cursor, esrc);

    // Layer 1
    gather_kernel<<<nblocks8, 256>>>((const float4*)x, rowptr, esrc, agg);
    gconv_tc_kernel<<<gblocks, 256, GC_SMEM_BYTES>>>((const float*)agg, x,
                                                     W1r, W1s, b1, (float*)ha, 1);
    // Layer 2
    gather_kernel<<<nblocks8, 256>>>((const float4*)ha, rowptr, esrc, agg);
    gconv_tc_kernel<<<gblocks, 256, GC_SMEM_BYTES>>>((const float*)agg, (const float*)ha,
                                                     W2r, W2s, b2, (float*)hb, 1);
    // Layer 3 (no relu)
    gather_kernel<<<nblocks8, 256>>>((const float4*)hb, rowptr, esrc, agg);
    gconv_tc_kernel<<<gblocks, 256, GC_SMEM_BYTES>>>((const float*)agg, (const float*)hb,
                                                     W3r, W3s, b3, (float*)ha, 0);

    // Fused mean-pool + classifier
    poolfinal_kernel<<<NG, FC>>>((const float*)ha, batch, Wl, bl, out);
}

// round 9
// speedup vs baseline: 3.4225x; 1.1040x over previous
#include <cuda_runtime.h>
#include <cuda_fp16.h>
#include <cstdint>

#define NN   100000
#define FC   128
#define NE   1600000
#define NG   512
#define NOUT 10
#define NSCAN (NN + 1)
#define SCAN_BLK 1024
#define NBLK ((NSCAN + SCAN_BLK - 1) / SCAN_BLK)   // 98

// Scratch (device globals)
__device__ float4 g_agg [(size_t)NN * (FC / 4)];
__device__ float4 g_ha  [(size_t)NN * (FC / 4)];
__device__ float4 g_hb  [(size_t)NN * (FC / 4)];
__device__ uint2  g_h16 [(size_t)NN * (FC / 4)];   // fp16 copy of current features
__device__ int    g_rowptr[NSCAN];
__device__ int    g_cursor[NN];
__device__ int    g_esrc[NE];
__device__ int    g_part[NBLK];
__device__ int    g_is64;

// ---------------------------------------------------------------------------
// Index dtype detection (int32 vs int64 edge/batch buffers)
// ---------------------------------------------------------------------------
__global__ void detect_kernel(const long long* __restrict__ ei)
{
    __shared__ int ok;
    if (threadIdx.x == 0) ok = 1;
    __syncthreads();
    long long v = ei[threadIdx.x];           // 512 threads
    if (v < 0 || v >= NN) atomicAnd(&ok, 0);
    __syncthreads();
    if (threadIdx.x == 0) g_is64 = ok;
}

__device__ __forceinline__ long long load_idx(const void* base, int i, int is64)
{
    if (is64) return ((const long long*)base)[i];
    return (long long)((const int*)base)[i];
}

// ---------------------------------------------------------------------------
// CSR build: histogram -> scan -> fill
// ---------------------------------------------------------------------------
__global__ void hist_kernel(const void* __restrict__ ei, int* __restrict__ deg)
{
    int is64 = g_is64;
    for (int e = blockIdx.x * blockDim.x + threadIdx.x; e < NE;
         e += gridDim.x * blockDim.x) {
        int d = (int)load_idx(ei, e + NE, is64);
        atomicAdd(&deg[d + 1], 1);
    }
}

__global__ void scanA_kernel(int* __restrict__ deg, int* __restrict__ part)
{
    __shared__ int sm[SCAN_BLK];
    int tid = threadIdx.x;
    int i = blockIdx.x * SCAN_BLK + tid;
    int v = (i < NSCAN) ? deg[i] : 0;
    sm[tid] = v;
    __syncthreads();
#pragma unroll
    for (int off = 1; off < SCAN_BLK; off <<= 1) {
        int t = (tid >= off) ? sm[tid - off] : 0;
        __syncthreads();
        sm[tid] += t;
        __syncthreads();
    }
    if (i < NSCAN) deg[i] = sm[tid];
    if (tid == SCAN_BLK - 1) part[blockIdx.x] = sm[tid];
}

__global__ void scanB_kernel(int* __restrict__ part)
{
    __shared__ int sm[128];
    int tid = threadIdx.x;   // 128 >= NBLK
    sm[tid] = (tid < NBLK) ? part[tid] : 0;
    __syncthreads();
#pragma unroll
    for (int off = 1; off < 128; off <<= 1) {
        int t = (tid >= off) ? sm[tid - off] : 0;
        __syncthreads();
        sm[tid] += t;
        __syncthreads();
    }
    if (tid < NBLK) part[tid] = sm[tid];
}

__global__ void scanC_kernel(int* __restrict__ deg, const int* __restrict__ part,
                             int* __restrict__ cursor)
{
    int i = blockIdx.x * SCAN_BLK + threadIdx.x;
    if (i < NSCAN) {
        int v = deg[i];
        if (blockIdx.x > 0) v += part[blockIdx.x - 1];
        deg[i] = v;
        if (i < NN) cursor[i] = v;
    }
}

__global__ void fill_kernel(const void* __restrict__ ei,
                            int* __restrict__ cursor, int* __restrict__ esrc)
{
    int is64 = g_is64;
    for (int e = blockIdx.x * blockDim.x + threadIdx.x; e < NE;
         e += gridDim.x * blockDim.x) {
        int s = (int)load_idx(ei, e, is64);
        int d = (int)load_idx(ei, e + NE, is64);
        int pos = atomicAdd(&cursor[d], 1);
        esrc[pos] = s;
    }
}

// ---------------------------------------------------------------------------
// fp32 -> fp16 convert (for layer-1 gather input)
// ---------------------------------------------------------------------------
__global__ void cvt16_kernel(const float4* __restrict__ src, uint2* __restrict__ dst)
{
    int i = blockIdx.x * blockDim.x + threadIdx.x;
    if (i >= NN * 32) return;
    float4 v = src[i];
    uint2 o;
    *(__half2*)&o.x = __floats2half2_rn(v.x, v.y);
    *(__half2*)&o.y = __floats2half2_rn(v.z, v.w);
    dst[i] = o;
}

// ---------------------------------------------------------------------------
// Atomic-free fp16 gather: agg[n] = sum_{j in row n} xh[esrc[j]]  (fp32 accum)
// One warp per node; lane c covers channels [4c, 4c+4).
// ---------------------------------------------------------------------------
__global__ void gather_h_kernel(const uint2* __restrict__ xh,
                                const int* __restrict__ rowptr,
                                const int* __restrict__ esrc,
                                float4* __restrict__ agg)
{
    int n = blockIdx.x * 8 + (threadIdx.x >> 5);
    if (n >= NN) return;
    int c = threadIdx.x & 31;
    int lo = __ldg(&rowptr[n]);
    int hi = __ldg(&rowptr[n + 1]);
    float4 a0 = make_float4(0.f, 0.f, 0.f, 0.f);
    float4 a1 = make_float4(0.f, 0.f, 0.f, 0.f);
    int j = lo;
    for (; j + 1 < hi; j += 2) {
        int s0 = __ldg(&esrc[j]);
        int s1 = __ldg(&esrc[j + 1]);
        uint2 v0 = xh[(long long)s0 * 32 + c];
        uint2 v1 = xh[(long long)s1 * 32 + c];
        float2 p0 = __half22float2(*(__half2*)&v0.x);
        float2 p1 = __half22float2(*(__half2*)&v0.y);
        float2 q0 = __half22float2(*(__half2*)&v1.x);
        float2 q1 = __half22float2(*(__half2*)&v1.y);
        a0.x += p0.x; a0.y += p0.y; a0.z += p1.x; a0.w += p1.y;
        a1.x += q0.x; a1.y += q0.y; a1.z += q1.x; a1.w += q1.y;
    }
    if (j < hi) {
        int s0 = __ldg(&esrc[j]);
        uint2 v0 = xh[(long long)s0 * 32 + c];
        float2 p0 = __half22float2(*(__half2*)&v0.x);
        float2 p1 = __half22float2(*(__half2*)&v0.y);
        a0.x += p0.x; a0.y += p0.y; a0.z += p1.x; a0.w += p1.y;
    }
    a0.x += a1.x; a0.y += a1.y; a0.z += a1.z; a0.w += a1.w;
    agg[(long long)n * 32 + c] = a0;
}

// ---------------------------------------------------------------------------
// Tensor-core GraphConv: out = (relu?)([A|X] @ [Wrel;Wroot] + b)
//   M=128/block, N=128, K=256, tf32 mma.m16n8k8.
//   Warp tile 32x64 (B fragments reused across 2 M-tiles -> fewer LDS).
//   Optionally emits packed-fp16 copy (out16) for the next layer's gather.
// ---------------------------------------------------------------------------
#define WSTRIDE 136
#define ASTRIDE 36
#define SW_WORDS (256 * WSTRIDE)
#define SA_WORDS (128 * ASTRIDE)
#define GC_SMEM_BYTES ((SW_WORDS + SA_WORDS) * 4)

__device__ __forceinline__ uint32_t f2tf32(float f)
{
    uint32_t r;
    asm("cvt.rna.tf32.f32 %0, %1;" : "=r"(r) : "f"(f));
    return r;
}

__device__ __forceinline__ void mma_tf32(float c[4],
                                         uint32_t a0, uint32_t a1,
                                         uint32_t a2, uint32_t a3,
                                         uint32_t b0, uint32_t b1)
{
    asm volatile("mma.sync.aligned.m16n8k8.row.col.f32.tf32.tf32.f32 "
                 "{%0,%1,%2,%3}, {%4,%5,%6,%7}, {%8,%9}, {%0,%1,%2,%3};"
                 : "+f"(c[0]), "+f"(c[1]), "+f"(c[2]), "+f"(c[3])
                 : "r"(a0), "r"(a1), "r"(a2), "r"(a3), "r"(b0), "r"(b1));
}

__global__ __launch_bounds__(256, 1) void gconv_tc_kernel(
    const float* __restrict__ A, const float* __restrict__ X,
    const float* __restrict__ Wrel, const float* __restrict__ Wroot,
    const float* __restrict__ bias, float* __restrict__ out,
    uint2* __restrict__ out16, int do_relu)
{
    extern __shared__ uint32_t smw[];
    uint32_t* sW = smw;               // 256 x 136 tf32 words
    uint32_t* sA = smw + SW_WORDS;    // 128 x 36  tf32 words

    const int tid  = threadIdx.x;
    const int warp = tid >> 5;
    const int lane = tid & 31;
    const int rowBase = blockIdx.x * 128;

    // warp tile: rows [wm, wm+32), cols [wn, wn+64)
    const int wm = (warp & 3) * 32;
    const int wn = (warp >> 2) * 64;
    const int g8 = lane >> 2;   // 0..7
    const int ak = lane & 3;    // 0..3

    // ---- Stage stacked weights [Wrel ; Wroot] into smem as tf32 ----
    for (int i = tid; i < 8192; i += 256) {
        int k  = i >> 5;
        int n4 = i & 31;
        const float* src = (k < 128) ? &Wrel[k * FC + n4 * 4]
                                     : &Wroot[(k - 128) * FC + n4 * 4];
        float4 w = *(const float4*)src;
        uint32_t* d = &sW[k * WSTRIDE + n4 * 4];
        d[0] = f2tf32(w.x); d[1] = f2tf32(w.y);
        d[2] = f2tf32(w.z); d[3] = f2tf32(w.w);
    }

    // ---- Stage chunk 0 of activations ----
    for (int j = 0; j < 4; j++) {
        int idx = tid + j * 256;
        int row = idx >> 3;
        int f4c = idx & 7;
        float4 v = make_float4(0.f, 0.f, 0.f, 0.f);
        int grow = rowBase + row;
        if (grow < NN)
            v = *(const float4*)&A[(size_t)grow * FC + f4c * 4];
        uint32_t* d = &sA[row * ASTRIDE + f4c * 4];
        d[0] = f2tf32(v.x); d[1] = f2tf32(v.y);
        d[2] = f2tf32(v.z); d[3] = f2tf32(v.w);
    }
    __syncthreads();

    float acc[2][8][4];
#pragma unroll
    for (int t = 0; t < 2; t++)
#pragma unroll
        for (int j = 0; j < 8; j++)
#pragma unroll
            for (int q = 0; q < 4; q++) acc[t][j][q] = 0.f;

    const int ar = (wm + g8) * ASTRIDE;

    float4 pf[4];
#pragma unroll 1
    for (int c = 0; c < 8; c++) {
        if (c < 7) {
            const float* srcM = (c + 1 < 4) ? A : X;
            int koff = ((c + 1) & 3) * 32;
#pragma unroll
            for (int j = 0; j < 4; j++) {
                int idx = tid + j * 256;
                int row = idx >> 3;
                int f4c = idx & 7;
                int grow = rowBase + row;
                pf[j] = (grow < NN)
                    ? *(const float4*)&srcM[(size_t)grow * FC + koff + f4c * 4]
                    : make_float4(0.f, 0.f, 0.f, 0.f);
            }
        }

#pragma unroll
        for (int ks = 0; ks < 4; ks++) {
            int kl = ks * 8;
            // A fragments for both 16-row tiles
            uint32_t a00 = sA[ar + kl + ak];
            uint32_t a01 = sA[ar + 8 * ASTRIDE + kl + ak];
            uint32_t a02 = sA[ar + kl + ak + 4];
            uint32_t a03 = sA[ar + 8 * ASTRIDE + kl + ak + 4];
            uint32_t a10 = sA[ar + 16 * ASTRIDE + kl + ak];
            uint32_t a11 = sA[ar + 24 * ASTRIDE + kl + ak];
            uint32_t a12 = sA[ar + 16 * ASTRIDE + kl + ak + 4];
            uint32_t a13 = sA[ar + 24 * ASTRIDE + kl + ak + 4];
            // B fragments for 8 n8-tiles (shared by both M tiles)
            int kg = c * 32 + kl;
            const uint32_t* bp = &sW[(kg + ak) * WSTRIDE + wn + g8];
            uint32_t b0[8], b1[8];
#pragma unroll
            for (int j = 0; j < 8; j++) {
                b0[j] = bp[j * 8];
                b1[j] = bp[j * 8 + 4 * WSTRIDE];
            }
#pragma unroll
            for (int j = 0; j < 8; j++)
                mma_tf32(acc[0][j], a00, a01, a02, a03, b0[j], b1[j]);
#pragma unroll
            for (int j = 0; j < 8; j++)
                mma_tf32(acc[1][j], a10, a11, a12, a13, b0[j], b1[j]);
        }
        __syncthreads();

        if (c < 7) {
#pragma unroll
            for (int j = 0; j < 4; j++) {
                int idx = tid + j * 256;
                int row = idx >> 3;
                int f4c = idx & 7;
                uint32_t* d = &sA[row * ASTRIDE + f4c * 4];
                d[0] = f2tf32(pf[j].x); d[1] = f2tf32(pf[j].y);
                d[2] = f2tf32(pf[j].z); d[3] = f2tf32(pf[j].w);
            }
            __syncthreads();
        }
    }

    // ---- Epilogue: bias (+relu), fp32 out (+ packed fp16 copy) ----
    const int coff = ak * 2;
    const int rbase = rowBase + wm + g8;
#pragma unroll
    for (int t = 0; t < 2; t++) {
        int ra = rbase + t * 16;
        int rb = ra + 8;
#pragma unroll
        for (int j = 0; j < 8; j++) {
            int col = wn + j * 8 + coff;
            float2 bb = *(const float2*)&bias[col];
            float2 o0, o1;
            o0.x = acc[t][j][0] + bb.x; o0.y = acc[t][j][1] + bb.y;
            o1.x = acc[t][j][2] + bb.x; o1.y = acc[t][j][3] + bb.y;
            if (do_relu) {
                o0.x = fmaxf(o0.x, 0.f); o0.y = fmaxf(o0.y, 0.f);
                o1.x = fmaxf(o1.x, 0.f); o1.y = fmaxf(o1.y, 0.f);
            }
            if (ra < NN) {
                *(float2*)&out[(size_t)ra * FC + col] = o0;
                if (out16)
                    *(__half2*)((uint32_t*)&out16[(size_t)ra * 32] + (col >> 1))
                        = __floats2half2_rn(o0.x, o0.y);
            }
            if (rb < NN) {
                *(float2*)&out[(size_t)rb * FC + col] = o1;
                if (out16)
                    *(__half2*)((uint32_t*)&out16[(size_t)rb * 32] + (col >> 1))
                        = __floats2half2_rn(o1.x, o1.y);
            }
        }
    }
}

// ---------------------------------------------------------------------------
// Fused mean-pool + classifier (batch sorted -> contiguous per-graph ranges)
// ---------------------------------------------------------------------------
__global__ void poolfinal_kernel(const float* __restrict__ h,
                                 const void* __restrict__ batch,
                                 const float* __restrict__ Wlin,
                                 const float* __restrict__ blin,
                                 float* __restrict__ out)
{
    __shared__ float sp[FC];
    __shared__ int bounds[2];
    int g = blockIdx.x;
    int t = threadIdx.x;
    int is64 = g_is64;

    if (t < 2) {
        long long target = g + t;
        int lo = 0, hi = NN;
        while (lo < hi) {
            int mid = (lo + hi) >> 1;
            if (load_idx(batch, mid, is64) < target) lo = mid + 1;
            else hi = mid;
        }
        bounds[t] = lo;
    }
    __syncthreads();
    int lo = bounds[0], hi = bounds[1];

    float s = 0.f;
    for (int n = lo; n < hi; n++)
        s += h[(size_t)n * FC + t];
    float inv = 1.0f / fmaxf((float)(hi - lo), 1.0f);
    sp[t] = s * inv;
    __syncthreads();

    if (t < NOUT) {
        float acc = blin[t];
#pragma unroll 16
        for (int k = 0; k < FC; k++)
            acc += sp[k] * Wlin[k * NOUT + t];
        out[g * NOUT + t] = acc;
    }
}

// ---------------------------------------------------------------------------
extern "C" void kernel_launch(void* const* d_in, const int* in_sizes, int n_in,
                              void* d_out, int out_size)
{
    const float* x     = (const float*)d_in[0];
    const void*  ei    = d_in[1];
    const void*  batch = d_in[2];
    const float* W1r = (const float*)d_in[3];
    const float* b1  = (const float*)d_in[4];
    const float* W1s = (const float*)d_in[5];
    const float* W2r = (const float*)d_in[6];
    const float* b2  = (const float*)d_in[7];
    const float* W2s = (const float*)d_in[8];
    const float* W3r = (const float*)d_in[9];
    const float* b3  = (const float*)d_in[10];
    const float* W3s = (const float*)d_in[11];
    const float* Wl  = (const float*)d_in[12];
    const float* bl  = (const float*)d_in[13];
    float* out = (float*)d_out;

    cudaFuncSetAttribute(gconv_tc_kernel,
                         cudaFuncAttributeMaxDynamicSharedMemorySize,
                         GC_SMEM_BYTES);

    float4 *agg, *ha, *hb;
    uint2 *h16;
    int *rowptr, *cursor, *esrc, *part;
    cudaGetSymbolAddress((void**)&agg,    g_agg);
    cudaGetSymbolAddress((void**)&ha,     g_ha);
    cudaGetSymbolAddress((void**)&hb,     g_hb);
    cudaGetSymbolAddress((void**)&h16,    g_h16);
    cudaGetSymbolAddress((void**)&rowptr, g_rowptr);
    cudaGetSymbolAddress((void**)&cursor, g_cursor);
    cudaGetSymbolAddress((void**)&esrc,   g_esrc);
    cudaGetSymbolAddress((void**)&part,   g_part);

    const int nblocks8 = (NN + 7) / 8;
    const int gblocks  = (NN + 127) / 128;
    const int cblocks  = (NN * 32 + 255) / 256;

    detect_kernel<<<1, 512>>>((const long long*)ei);

    // ---- CSR build (once, reused by all 3 layers) ----
    cudaMemsetAsync(rowptr, 0, NSCAN * sizeof(int));
    hist_kernel<<<2048, 256>>>(ei, rowptr);
    scanA_kernel<<<NBLK, SCAN_BLK>>>(rowptr, part);
    scanB_kernel<<<1, 128>>>(part);
    scanC_kernel<<<NBLK, SCAN_BLK>>>(rowptr, part, cursor);
    fill_kernel<<<2048, 256>>>(ei, cursor, esrc);

    // fp16 copy of x for layer-1 gather
    cvt16_kernel<<<cblocks, 256>>>((const float4*)x, h16);

    // Layer 1 (gconv writes ha + fresh h16 for next gather)
    gather_h_kernel<<<nblocks8, 256>>>(h16, rowptr, esrc, agg);
    gconv_tc_kernel<<<gblocks, 256, GC_SMEM_BYTES>>>((const float*)agg, x,
                                                     W1r, W1s, b1, (float*)ha, h16, 1);
    // Layer 2
    gather_h_kernel<<<nblocks8, 256>>>(h16, rowptr, esrc, agg);
    gconv_tc_kernel<<<gblocks, 256, GC_SMEM_BYTES>>>((const float*)agg, (const float*)ha,
                                                     W2r, W2s, b2, (float*)hb, h16, 1);
    // Layer 3 (no relu, no fp16 copy needed)
    gather_h_kernel<<<nblocks8, 256>>>(h16, rowptr, esrc, agg);
    gconv_tc_kernel<<<gblocks, 256, GC_SMEM_BYTES>>>((const float*)agg, (const float*)hb,
                                                     W3r, W3s, b3, (float*)ha, (uint2*)0, 0);

    // Fused mean-pool + classifier
    poolfinal_kernel<<<NG, FC>>>((const float*)ha, batch, Wl, bl, out);
}

// round 10
// speedup vs baseline: 4.5623x; 1.3331x over previous
#include <cuda_runtime.h>
#include <cuda_fp16.h>
#include <cstdint>

#define NN   100000
#define FC   128
#define NE   1600000
#define NG   512
#define NOUT 10
#define NSCAN (NN + 1)
#define SCAN_BLK 1024
#define NBLK ((NSCAN + SCAN_BLK - 1) / SCAN_BLK)   // 98

// Scratch (device globals)
__device__ uint2  g_agg16[(size_t)NN * 32];   // fp16 aggregate  [NN][64 words]
__device__ uint2  g_f16a [(size_t)NN * 32];   // fp16 features ping
__device__ uint2  g_f16b [(size_t)NN * 32];   // fp16 features pong
__device__ float4 g_ha   [(size_t)NN * (FC / 4)];   // fp32 layer-3 output
__device__ int    g_rowptr[NSCAN];
__device__ int    g_cursor[NN];
__device__ int    g_esrc[NE];
__device__ int    g_part[NBLK];
__device__ int    g_is64;

// ---------------------------------------------------------------------------
// Index dtype detection (int32 vs int64 edge/batch buffers)
// ---------------------------------------------------------------------------
__global__ void detect_kernel(const long long* __restrict__ ei)
{
    __shared__ int ok;
    if (threadIdx.x == 0) ok = 1;
    __syncthreads();
    long long v = ei[threadIdx.x];           // 512 threads
    if (v < 0 || v >= NN) atomicAnd(&ok, 0);
    __syncthreads();
    if (threadIdx.x == 0) g_is64 = ok;
}

__device__ __forceinline__ long long load_idx(const void* base, int i, int is64)
{
    if (is64) return ((const long long*)base)[i];
    return (long long)((const int*)base)[i];
}

// ---------------------------------------------------------------------------
// CSR build: histogram -> scan -> fill
// ---------------------------------------------------------------------------
__global__ void hist_kernel(const void* __restrict__ ei, int* __restrict__ deg)
{
    int is64 = g_is64;
    for (int e = blockIdx.x * blockDim.x + threadIdx.x; e < NE;
         e += gridDim.x * blockDim.x) {
        int d = (int)load_idx(ei, e + NE, is64);
        atomicAdd(&deg[d + 1], 1);
    }
}

__global__ void scanA_kernel(int* __restrict__ deg, int* __restrict__ part)
{
    __shared__ int sm[SCAN_BLK];
    int tid = threadIdx.x;
    int i = blockIdx.x * SCAN_BLK + tid;
    int v = (i < NSCAN) ? deg[i] : 0;
    sm[tid] = v;
    __syncthreads();
#pragma unroll
    for (int off = 1; off < SCAN_BLK; off <<= 1) {
        int t = (tid >= off) ? sm[tid - off] : 0;
        __syncthreads();
        sm[tid] += t;
        __syncthreads();
    }
    if (i < NSCAN) deg[i] = sm[tid];
    if (tid == SCAN_BLK - 1) part[blockIdx.x] = sm[tid];
}

__global__ void scanB_kernel(int* __restrict__ part)
{
    __shared__ int sm[128];
    int tid = threadIdx.x;
    sm[tid] = (tid < NBLK) ? part[tid] : 0;
    __syncthreads();
#pragma unroll
    for (int off = 1; off < 128; off <<= 1) {
        int t = (tid >= off) ? sm[tid - off] : 0;
        __syncthreads();
        sm[tid] += t;
        __syncthreads();
    }
    if (tid < NBLK) part[tid] = sm[tid];
}

__global__ void scanC_kernel(int* __restrict__ deg, const int* __restrict__ part,
                             int* __restrict__ cursor)
{
    int i = blockIdx.x * SCAN_BLK + threadIdx.x;
    if (i < NSCAN) {
        int v = deg[i];
        if (blockIdx.x > 0) v += part[blockIdx.x - 1];
        deg[i] = v;
        if (i < NN) cursor[i] = v;
    }
}

__global__ void fill_kernel(const void* __restrict__ ei,
                            int* __restrict__ cursor, int* __restrict__ esrc)
{
    int is64 = g_is64;
    for (int e = blockIdx.x * blockDim.x + threadIdx.x; e < NE;
         e += gridDim.x * blockDim.x) {
        int s = (int)load_idx(ei, e, is64);
        int d = (int)load_idx(ei, e + NE, is64);
        int pos = atomicAdd(&cursor[d], 1);
        esrc[pos] = s;
    }
}

// ---------------------------------------------------------------------------
// fp32 -> fp16 convert
// ---------------------------------------------------------------------------
__global__ void cvt16_kernel(const float4* __restrict__ src, uint2* __restrict__ dst)
{
    int i = blockIdx.x * blockDim.x + threadIdx.x;
    if (i >= NN * 32) return;
    float4 v = src[i];
    uint2 o;
    *(__half2*)&o.x = __floats2half2_rn(v.x, v.y);
    *(__half2*)&o.y = __floats2half2_rn(v.z, v.w);
    dst[i] = o;
}

// ---------------------------------------------------------------------------
// Atomic-free fp16 gather: agg16[n] = sum_{j in row n} xh[esrc[j]]
// fp32 accumulation, fp16 output. One warp per node; lane c: channels [4c,4c+4)
// ---------------------------------------------------------------------------
__global__ void gather_h_kernel(const uint2* __restrict__ xh,
                                const int* __restrict__ rowptr,
                                const int* __restrict__ esrc,
                                uint2* __restrict__ agg16)
{
    int n = blockIdx.x * 8 + (threadIdx.x >> 5);
    if (n >= NN) return;
    int c = threadIdx.x & 31;
    int lo = __ldg(&rowptr[n]);
    int hi = __ldg(&rowptr[n + 1]);
    float4 a0 = make_float4(0.f, 0.f, 0.f, 0.f);
    float4 a1 = make_float4(0.f, 0.f, 0.f, 0.f);
    int j = lo;
    for (; j + 1 < hi; j += 2) {
        int s0 = __ldg(&esrc[j]);
        int s1 = __ldg(&esrc[j + 1]);
        uint2 v0 = xh[(long long)s0 * 32 + c];
        uint2 v1 = xh[(long long)s1 * 32 + c];
        float2 p0 = __half22float2(*(__half2*)&v0.x);
        float2 p1 = __half22float2(*(__half2*)&v0.y);
        float2 q0 = __half22float2(*(__half2*)&v1.x);
        float2 q1 = __half22float2(*(__half2*)&v1.y);
        a0.x += p0.x; a0.y += p0.y; a0.z += p1.x; a0.w += p1.y;
        a1.x += q0.x; a1.y += q0.y; a1.z += q1.x; a1.w += q1.y;
    }
    if (j < hi) {
        int s0 = __ldg(&esrc[j]);
        uint2 v0 = xh[(long long)s0 * 32 + c];
        float2 p0 = __half22float2(*(__half2*)&v0.x);
        float2 p1 = __half22float2(*(__half2*)&v0.y);
        a0.x += p0.x; a0.y += p0.y; a0.z += p1.x; a0.w += p1.y;
    }
    uint2 o;
    *(__half2*)&o.x = __floats2half2_rn(a0.x + a1.x, a0.y + a1.y);
    *(__half2*)&o.y = __floats2half2_rn(a0.z + a1.z, a0.w + a1.w);
    agg16[(long long)n * 32 + c] = o;
}

// ---------------------------------------------------------------------------
// fp16 tensor-core GraphConv: out = (relu?)([A|X] @ [Wrel;Wroot] + b)
//   M=128/block, N=128, K=256, fp16 mma.m16n8k16, fp32 accumulate.
//   Weights half2-packed along k in smem (stride 136 words).
//   Activations staged per 32-k chunk (stride 20 words), register prefetch.
//   2 blocks/SM (80KB smem). Emits fp16 and/or fp32 outputs.
// ---------------------------------------------------------------------------
#define WS2 136
#define AS2 20
#define SWH_WORDS (128 * WS2)    // 17408
#define SAH_WORDS (128 * AS2)    //  2560
#define GC_SMEM_BYTES ((SWH_WORDS + SAH_WORDS) * 4)

__device__ __forceinline__ void mma_f16(float c[4],
                                        uint32_t a0, uint32_t a1,
                                        uint32_t a2, uint32_t a3,
                                        uint32_t b0, uint32_t b1)
{
    asm volatile("mma.sync.aligned.m16n8k16.row.col.f32.f16.f16.f32 "
                 "{%0,%1,%2,%3}, {%4,%5,%6,%7}, {%8,%9}, {%0,%1,%2,%3};"
                 : "+f"(c[0]), "+f"(c[1]), "+f"(c[2]), "+f"(c[3])
                 : "r"(a0), "r"(a1), "r"(a2), "r"(a3), "r"(b0), "r"(b1));
}

__global__ __launch_bounds__(256, 2) void gconv_h_kernel(
    const uint4* __restrict__ Ah, const uint4* __restrict__ Xh,
    const float* __restrict__ Wrel, const float* __restrict__ Wroot,
    const float* __restrict__ bias, float* __restrict__ out32,
    uint32_t* __restrict__ out16, int do_relu)
{
    extern __shared__ uint32_t smw[];
    uint32_t* sW = smw;               // [k2 0..127][n 0..127] stride 136
    uint32_t* sA = smw + SWH_WORDS;   // [row 0..127][k2 0..15] stride 20

    const int tid  = threadIdx.x;
    const int warp = tid >> 5;
    const int lane = tid & 31;
    const int rowBase = blockIdx.x * 128;

    const int wm = (warp & 3) * 32;   // warp rows [wm, wm+32)
    const int wn = (warp >> 2) * 64;  // warp cols [wn, wn+64)
    const int g8 = lane >> 2;
    const int ak = lane & 3;

    // ---- Stage stacked weights as half2(k even, k odd) ----
    for (int i = tid; i < 4096; i += 256) {
        int k2 = i >> 5;          // 0..127
        int n4 = i & 31;
        const float* r0 = (k2 < 64) ? &Wrel[(2 * k2) * FC + n4 * 4]
                                    : &Wroot[(2 * k2 - 128) * FC + n4 * 4];
        float4 w0 = *(const float4*)r0;
        float4 w1 = *(const float4*)(r0 + FC);
        uint32_t* d = &sW[k2 * WS2 + n4 * 4];
        *(__half2*)&d[0] = __floats2half2_rn(w0.x, w1.x);
        *(__half2*)&d[1] = __floats2half2_rn(w0.y, w1.y);
        *(__half2*)&d[2] = __floats2half2_rn(w0.z, w1.z);
        *(__half2*)&d[3] = __floats2half2_rn(w0.w, w1.w);
    }

    // ---- Stage chunk 0 (k [0,32) of agg) ----
    // idx 0..511: row = idx>>2, q = idx&3 -> one uint4 (4 words = 8 halves)
#pragma unroll
    for (int r = 0; r < 2; r++) {
        int idx = tid + r * 256;
        int row = idx >> 2;
        int q   = idx & 3;
        int grow = rowBase + row;
        uint4 v = make_uint4(0, 0, 0, 0);
        if (grow < NN) v = Ah[(size_t)grow * 16 + q];
        uint32_t* d = &sA[row * AS2 + q * 4];
        d[0] = v.x; d[1] = v.y; d[2] = v.z; d[3] = v.w;
    }
    __syncthreads();

    float acc[2][8][4];
#pragma unroll
    for (int t = 0; t < 2; t++)
#pragma unroll
        for (int j = 0; j < 8; j++)
#pragma unroll
            for (int q = 0; q < 4; q++) acc[t][j][q] = 0.f;

    const int ar = (wm + g8) * AS2;

    uint4 pf[2];
#pragma unroll 1
    for (int c = 0; c < 8; c++) {
        // prefetch next chunk
        if (c < 7) {
            const uint4* src = (c + 1 < 4) ? Ah : Xh;
            int cq = ((c + 1) & 3) * 4;
#pragma unroll
            for (int r = 0; r < 2; r++) {
                int idx = tid + r * 256;
                int row = idx >> 2;
                int q   = idx & 3;
                int grow = rowBase + row;
                pf[r] = (grow < NN) ? src[(size_t)grow * 16 + cq + q]
                                    : make_uint4(0, 0, 0, 0);
            }
        }

        // 2 ksteps (k16 each) over this 32-k chunk
#pragma unroll
        for (int s = 0; s < 2; s++) {
            int kl = s * 8;                 // local k2 base
            uint32_t a00 = sA[ar + kl + ak];
            uint32_t a01 = sA[ar + 8 * AS2 + kl + ak];
            uint32_t a02 = sA[ar + kl + ak + 4];
            uint32_t a03 = sA[ar + 8 * AS2 + kl + ak + 4];
            uint32_t a10 = sA[ar + 16 * AS2 + kl + ak];
            uint32_t a11 = sA[ar + 24 * AS2 + kl + ak];
            uint32_t a12 = sA[ar + 16 * AS2 + kl + ak + 4];
            uint32_t a13 = sA[ar + 24 * AS2 + kl + ak + 4];
            int kg2 = c * 16 + kl;          // global k2 base
            const uint32_t* bp = &sW[(kg2 + ak) * WS2 + wn + g8];
            uint32_t b0[8], b1[8];
#pragma unroll
            for (int j = 0; j < 8; j++) {
                b0[j] = bp[j * 8];
                b1[j] = bp[j * 8 + 4 * WS2];
            }
#pragma unroll
            for (int j = 0; j < 8; j++)
                mma_f16(acc[0][j], a00, a01, a02, a03, b0[j], b1[j]);
#pragma unroll
            for (int j = 0; j < 8; j++)
                mma_f16(acc[1][j], a10, a11, a12, a13, b0[j], b1[j]);
        }
        __syncthreads();

        if (c < 7) {
#pragma unroll
            for (int r = 0; r < 2; r++) {
                int idx = tid + r * 256;
                int row = idx >> 2;
                int q   = idx & 3;
                uint32_t* d = &sA[row * AS2 + q * 4];
                d[0] = pf[r].x; d[1] = pf[r].y; d[2] = pf[r].z; d[3] = pf[r].w;
            }
            __syncthreads();
        }
    }

    // ---- Epilogue: bias (+relu); fp16 and/or fp32 stores ----
    const int coff = ak * 2;
    const int rbase = rowBase + wm + g8;
#pragma unroll
    for (int t = 0; t < 2; t++) {
        int ra = rbase + t * 16;
        int rb = ra + 8;
#pragma unroll
        for (int j = 0; j < 8; j++) {
            int col = wn + j * 8 + coff;
            float2 bb = *(const float2*)&bias[col];
            float2 o0, o1;
            o0.x = acc[t][j][0] + bb.x; o0.y = acc[t][j][1] + bb.y;
            o1.x = acc[t][j][2] + bb.x; o1.y = acc[t][j][3] + bb.y;
            if (do_relu) {
                o0.x = fmaxf(o0.x, 0.f); o0.y = fmaxf(o0.y, 0.f);
                o1.x = fmaxf(o1.x, 0.f); o1.y = fmaxf(o1.y, 0.f);
            }
            if (ra < NN) {
                if (out16)
                    *(__half2*)&out16[(size_t)ra * 64 + (col >> 1)]
                        = __floats2half2_rn(o0.x, o0.y);
                if (out32) *(float2*)&out32[(size_t)ra * FC + col] = o0;
            }
            if (rb < NN) {
                if (out16)
                    *(__half2*)&out16[(size_t)rb * 64 + (col >> 1)]
                        = __floats2half2_rn(o1.x, o1.y);
                if (out32) *(float2*)&out32[(size_t)rb * FC + col] = o1;
            }
        }
    }
}

// ---------------------------------------------------------------------------
// Fused mean-pool + classifier (batch sorted -> contiguous per-graph ranges)
// ---------------------------------------------------------------------------
__global__ void poolfinal_kernel(const float* __restrict__ h,
                                 const void* __restrict__ batch,
                                 const float* __restrict__ Wlin,
                                 const float* __restrict__ blin,
                                 float* __restrict__ out)
{
    __shared__ float sp[FC];
    __shared__ int bounds[2];
    int g = blockIdx.x;
    int t = threadIdx.x;
    int is64 = g_is64;

    if (t < 2) {
        long long target = g + t;
        int lo = 0, hi = NN;
        while (lo < hi) {
            int mid = (lo + hi) >> 1;
            if (load_idx(batch, mid, is64) < target) lo = mid + 1;
            else hi = mid;
        }
        bounds[t] = lo;
    }
    __syncthreads();
    int lo = bounds[0], hi = bounds[1];

    float s = 0.f;
    for (int n = lo; n < hi; n++)
        s += h[(size_t)n * FC + t];
    float inv = 1.0f / fmaxf((float)(hi - lo), 1.0f);
    sp[t] = s * inv;
    __syncthreads();

    if (t < NOUT) {
        float acc = blin[t];
#pragma unroll 16
        for (int k = 0; k < FC; k++)
            acc += sp[k] * Wlin[k * NOUT + t];
        out[g * NOUT + t] = acc;
    }
}

// ---------------------------------------------------------------------------
extern "C" void kernel_launch(void* const* d_in, const int* in_sizes, int n_in,
                              void* d_out, int out_size)
{
    const float* x     = (const float*)d_in[0];
    const void*  ei    = d_in[1];
    const void*  batch = d_in[2];
    const float* W1r = (const float*)d_in[3];
    const float* b1  = (const float*)d_in[4];
    const float* W1s = (const float*)d_in[5];
    const float* W2r = (const float*)d_in[6];
    const float* b2  = (const float*)d_in[7];
    const float* W2s = (const float*)d_in[8];
    const float* W3r = (const float*)d_in[9];
    const float* b3  = (const float*)d_in[10];
    const float* W3s = (const float*)d_in[11];
    const float* Wl  = (const float*)d_in[12];
    const float* bl  = (const float*)d_in[13];
    float* out = (float*)d_out;

    cudaFuncSetAttribute(gconv_h_kernel,
                         cudaFuncAttributeMaxDynamicSharedMemorySize,
                         GC_SMEM_BYTES);

    uint2 *agg16, *f16a, *f16b;
    float4 *ha;
    int *rowptr, *cursor, *esrc, *part;
    cudaGetSymbolAddress((void**)&agg16,  g_agg16);
    cudaGetSymbolAddress((void**)&f16a,   g_f16a);
    cudaGetSymbolAddress((void**)&f16b,   g_f16b);
    cudaGetSymbolAddress((void**)&ha,     g_ha);
    cudaGetSymbolAddress((void**)&rowptr, g_rowptr);
    cudaGetSymbolAddress((void**)&cursor, g_cursor);
    cudaGetSymbolAddress((void**)&esrc,   g_esrc);
    cudaGetSymbolAddress((void**)&part,   g_part);

    const int nblocks8 = (NN + 7) / 8;
    const int gblocks  = (NN + 127) / 128;
    const int cblocks  = (NN * 32 + 255) / 256;

    detect_kernel<<<1, 512>>>((const long long*)ei);

    // ---- CSR build ----
    cudaMemsetAsync(rowptr, 0, NSCAN * sizeof(int));
    hist_kernel<<<2048, 256>>>(ei, rowptr);
    scanA_kernel<<<NBLK, SCAN_BLK>>>(rowptr, part);
    scanB_kernel<<<1, 128>>>(part);
    scanC_kernel<<<NBLK, SCAN_BLK>>>(rowptr, part, cursor);
    fill_kernel<<<2048, 256>>>(ei, cursor, esrc);

    // fp16 copy of x
    cvt16_kernel<<<cblocks, 256>>>((const float4*)x, f16a);

    // Layer 1: f16a -> f16b
    gather_h_kernel<<<nblocks8, 256>>>(f16a, rowptr, esrc, agg16);
    gconv_h_kernel<<<gblocks, 256, GC_SMEM_BYTES>>>(
        (const uint4*)agg16, (const uint4*)f16a, W1r, W1s, b1,
        (float*)0, (uint32_t*)f16b, 1);
    // Layer 2: f16b -> f16a
    gather_h_kernel<<<nblocks8, 256>>>(f16b, rowptr, esrc, agg16);
    gconv_h_kernel<<<gblocks, 256, GC_SMEM_BYTES>>>(
        (const uint4*)agg16, (const uint4*)f16b, W2r, W2s, b2,
        (float*)0, (uint32_t*)f16a, 1);
    // Layer 3: f16a -> fp32 ha (no relu)
    gather_h_kernel<<<nblocks8, 256>>>(f16a, rowptr, esrc, agg16);
    gconv_h_kernel<<<gblocks, 256, GC_SMEM_BYTES>>>(
        (const uint4*)agg16, (const uint4*)f16a, W3r, W3s, b3,
        (float*)ha, (uint32_t*)0, 0);

    // Fused mean-pool + classifier
    poolfinal_kernel<<<NG, FC>>>((const float*)ha, batch, Wl, bl, out);
}